// round 5
// baseline (speedup 1.0000x reference)
#include <cuda_runtime.h>
#include <math.h>

#define N_NODES 40962
#define N_EDGES 245760
#define KG 10
#define GMM_EPS 1e-15f
#define K1 704      // 640 (agg1) + 64 (x row -> root1)
#define K2 1408     // 640 (agg2) + 64 (h) + 640 (aggs) + 64 (x)

// ---------------- scratch (device globals; no runtime allocation) -------------
__device__ int   d_cnt[N_NODES];
__device__ int   d_cur[N_NODES];
__device__ int   d_offs[N_NODES + 1];
__device__ float d_dinv[N_NODES];
__device__ int   d_ssrc[N_EDGES];
__device__ float d_wA[(size_t)N_EDGES * KG];        // conv1 weights (pre-scaled by dinv)
__device__ float d_wB[(size_t)N_EDGES * 2 * KG];    // conv2 | shortcut weights (pre-scaled)
__device__ float d_t1[(size_t)N_NODES * K1];
__device__ float d_t2[(size_t)N_NODES * K2];
__device__ float d_h [(size_t)N_NODES * 64];
__device__ float d_B1[K1 * 64];
__device__ float d_B2[K2 * 128];
__device__ float d_bias2[128];

// ---------------- prep kernels ------------------------------------------------
__global__ void zero_cnt() {
    int i = blockIdx.x * blockDim.x + threadIdx.x;
    if (i < N_NODES) { d_cnt[i] = 0; d_cur[i] = 0; }
}

__global__ void hist_dst(const int* __restrict__ ei) {
    int e = blockIdx.x * blockDim.x + threadIdx.x;
    if (e < N_EDGES) atomicAdd(&d_cnt[ei[N_EDGES + e]], 1);
}

// single block, register-serial scan: each thread owns 41 contiguous counts
#define SCAN_C 41
__global__ __launch_bounds__(1024) void scan_deg() {
    __shared__ int sh[32];
    int t = threadIdx.x, lane = t & 31, wid = t >> 5;
    int base = t * SCAN_C;
    int vals[SCAN_C];
    int sum = 0;
    #pragma unroll
    for (int j = 0; j < SCAN_C; ++j) {
        int i = base + j;
        int v = (i < N_NODES) ? d_cnt[i] : 0;
        vals[j] = sum;
        sum += v;
        if (i < N_NODES) d_dinv[i] = 1.0f / (float)max(v, 1);
    }
    int s = sum;
    #pragma unroll
    for (int off = 1; off < 32; off <<= 1) {
        int n = __shfl_up_sync(0xffffffffu, s, off);
        if (lane >= off) s += n;
    }
    if (lane == 31) sh[wid] = s;
    __syncthreads();
    if (wid == 0) {
        int w = sh[lane];
        #pragma unroll
        for (int off = 1; off < 32; off <<= 1) {
            int n = __shfl_up_sync(0xffffffffu, w, off);
            if (lane >= off) w += n;
        }
        sh[lane] = w;
    }
    __syncthreads();
    int excl = s - sum + (wid > 0 ? sh[wid - 1] : 0);
    #pragma unroll
    for (int j = 0; j < SCAN_C; ++j) {
        int i = base + j;
        if (i < N_NODES) d_offs[i] = excl + vals[j];
    }
    if (t == 0) d_offs[N_NODES] = N_EDGES;
}

// weave both big B matrices + combined bias
__global__ void bweave(const float* __restrict__ g1, const float* __restrict__ root1,
                       const float* __restrict__ g2, const float* __restrict__ root2,
                       const float* __restrict__ gs, const float* __restrict__ roots,
                       const float* __restrict__ b2, const float* __restrict__ bs) {
    int idx = blockIdx.x * blockDim.x + threadIdx.x;
    if (idx < 128) d_bias2[idx] = b2[idx] + bs[idx];
    if (idx < K1 * 64) {
        int r = idx >> 6, c = idx & 63;
        float v;
        if (r < 640) { int k = r >> 6, cin = r & 63; v = g1[cin * 640 + k * 64 + c]; }
        else         { v = root1[(r - 640) * 64 + c]; }
        d_B1[idx] = v;
    }
    if (idx < K2 * 128) {
        int r = idx >> 7, c = idx & 127;
        float v;
        if (r < 640)       { int k = r >> 6, cin = r & 63; v = g2[cin * 1280 + k * 128 + c]; }
        else if (r < 704)  { v = root2[(r - 640) * 128 + c]; }
        else if (r < 1344) { int rr = r - 704; int k = rr >> 6, cin = rr & 63; v = gs[cin * 1280 + k * 128 + c]; }
        else               { v = roots[(r - 1344) * 128 + c]; }
        d_B2[idx] = v;
    }
}

// ---------------- gaussian weights + dst-sort scatter (dinv folded in) --------
__device__ __forceinline__ float gweight(float p0, float p1,
                                         const float* __restrict__ mu,
                                         const float* __restrict__ sg, int k) {
    float dx = p0 - mu[2 * k], dy = p1 - mu[2 * k + 1];
    float s0 = sg[2 * k],      s1 = sg[2 * k + 1];
    return __expf(-0.5f * dx * dx / (GMM_EPS + s0 * s0)
                  - 0.5f * dy * dy / (GMM_EPS + s1 * s1));
}

__global__ void scatterw(const int* __restrict__ ei, const float* __restrict__ pseudo,
                         const float* __restrict__ mu1, const float* __restrict__ sg1,
                         const float* __restrict__ mu2, const float* __restrict__ sg2,
                         const float* __restrict__ mus, const float* __restrict__ sgs) {
    int e = blockIdx.x * blockDim.x + threadIdx.x;
    if (e >= N_EDGES) return;
    int src = ei[e];
    int dst = ei[N_EDGES + e];
    float p0 = pseudo[2 * e], p1 = pseudo[2 * e + 1];
    int pos = d_offs[dst] + atomicAdd(&d_cur[dst], 1);
    d_ssrc[pos] = src;
    float dinv = d_dinv[dst];
    #pragma unroll
    for (int k = 0; k < KG; ++k) {
        d_wA[(size_t)pos * KG + k]          = gweight(p0, p1, mu1, sg1, k) * dinv;
        d_wB[(size_t)pos * 2 * KG + k]      = gweight(p0, p1, mu2, sg2, k) * dinv;
        d_wB[(size_t)pos * 2 * KG + KG + k] = gweight(p0, p1, mus, sgs, k) * dinv;
    }
}

// ---------------- t-builds (warp per dst node, CSR) ---------------------------
__global__ __launch_bounds__(256) void tbuild1(const float* __restrict__ x) {
    int gw = (blockIdx.x * blockDim.x + threadIdx.x) >> 5;
    int lane = threadIdx.x & 31;
    if (gw >= N_NODES) return;
    int beg = d_offs[gw], end = d_offs[gw + 1];
    float a[KG][2];
    #pragma unroll
    for (int k = 0; k < KG; ++k) { a[k][0] = 0.f; a[k][1] = 0.f; }
    for (int e = beg; e < end; ++e) {
        int s = d_ssrc[e];
        float wv = (lane < KG) ? d_wA[(size_t)e * KG + lane] : 0.f;
        float x0 = x[(size_t)s * 64 + lane];
        float x1 = x[(size_t)s * 64 + 32 + lane];
        #pragma unroll
        for (int k = 0; k < KG; ++k) {
            float w = __shfl_sync(0xffffffffu, wv, k);
            a[k][0] = fmaf(w, x0, a[k][0]);
            a[k][1] = fmaf(w, x1, a[k][1]);
        }
    }
    float* tr = d_t1 + (size_t)gw * K1;
    #pragma unroll
    for (int k = 0; k < KG; ++k) {
        tr[k * 64 + lane]      = a[k][0];
        tr[k * 64 + 32 + lane] = a[k][1];
    }
    tr[640 + lane]      = x[(size_t)gw * 64 + lane];
    tr[640 + 32 + lane] = x[(size_t)gw * 64 + 32 + lane];
}

__global__ __launch_bounds__(256) void tbuild2(const float* __restrict__ x) {
    int gw = (blockIdx.x * blockDim.x + threadIdx.x) >> 5;
    int lane = threadIdx.x & 31;
    if (gw >= N_NODES) return;
    int beg = d_offs[gw], end = d_offs[gw + 1];
    float a2[KG][2], as_[KG][2];
    #pragma unroll
    for (int k = 0; k < KG; ++k) { a2[k][0]=0.f; a2[k][1]=0.f; as_[k][0]=0.f; as_[k][1]=0.f; }
    for (int e = beg; e < end; ++e) {
        int s = d_ssrc[e];
        float wv = (lane < 2 * KG) ? d_wB[(size_t)e * 2 * KG + lane] : 0.f;
        float h0 = d_h[(size_t)s * 64 + lane];
        float h1 = d_h[(size_t)s * 64 + 32 + lane];
        float x0 = x[(size_t)s * 64 + lane];
        float x1 = x[(size_t)s * 64 + 32 + lane];
        #pragma unroll
        for (int k = 0; k < KG; ++k) {
            float w2 = __shfl_sync(0xffffffffu, wv, k);
            float ws = __shfl_sync(0xffffffffu, wv, KG + k);
            a2[k][0]  = fmaf(w2, h0, a2[k][0]);
            a2[k][1]  = fmaf(w2, h1, a2[k][1]);
            as_[k][0] = fmaf(ws, x0, as_[k][0]);
            as_[k][1] = fmaf(ws, x1, as_[k][1]);
        }
    }
    float* tr = d_t2 + (size_t)gw * K2;
    #pragma unroll
    for (int k = 0; k < KG; ++k) {
        tr[k * 64 + lane]            = a2[k][0];
        tr[k * 64 + 32 + lane]       = a2[k][1];
        tr[704 + k * 64 + lane]      = as_[k][0];
        tr[704 + k * 64 + 32 + lane] = as_[k][1];
    }
    tr[640 + lane]       = d_h[(size_t)gw * 64 + lane];
    tr[640 + 32 + lane]  = d_h[(size_t)gw * 64 + 32 + lane];
    tr[1344 + lane]      = x[(size_t)gw * 64 + lane];
    tr[1344 + 32 + lane] = x[(size_t)gw * 64 + 32 + lane];
}

// ---------------- tf32 helpers ------------------------------------------------
__device__ __forceinline__ unsigned f2tf32(float x) {
    unsigned r;
    asm("cvt.rna.tf32.f32 %0, %1;" : "=r"(r) : "f"(x));
    return r;
}
__device__ __forceinline__ unsigned fu(float x) { return __float_as_uint(x); }

// ---------------- GEMM A: BM=64, BN=64 (layer 1, N=64) ------------------------
__global__ __launch_bounds__(256) void gemm64(
    const float* __restrict__ A, const float* __restrict__ B,
    float* __restrict__ C, int M, int N, int K, const float* __restrict__ bias)
{
    __shared__ float As[64][68];
    __shared__ float Bs[64][72];
    const int tid = threadIdx.x;
    const int bm = blockIdx.y * 64;
    const int bn = blockIdx.x * 64;
    const int wid = tid >> 5, l = tid & 31;
    const int wr = wid & 3, wc = wid >> 2;
    const int tg = l >> 2, ti = l & 3;

    float acc[4][4] = {};
    for (int kc = 0; kc < K; kc += 64) {
        {
            int row = tid >> 2, cq = (tid & 3) * 16;
            bool av = (bm + row) < M;
            const float* ap = A + (size_t)(bm + row) * K + kc + cq;
            #pragma unroll
            for (int j = 0; j < 4; ++j) {
                float4 v = av ? *(const float4*)(ap + 4 * j) : make_float4(0.f,0.f,0.f,0.f);
                As[row][cq+4*j+0] = __uint_as_float(f2tf32(v.x));
                As[row][cq+4*j+1] = __uint_as_float(f2tf32(v.y));
                As[row][cq+4*j+2] = __uint_as_float(f2tf32(v.z));
                As[row][cq+4*j+3] = __uint_as_float(f2tf32(v.w));
            }
        }
        {
            int k = tid >> 2, nq = (tid & 3) * 16;
            const float* bp = B + (size_t)(kc + k) * N + bn + nq;
            #pragma unroll
            for (int j = 0; j < 4; ++j) {
                float4 v = *(const float4*)(bp + 4 * j);
                Bs[k][nq+4*j+0] = __uint_as_float(f2tf32(v.x));
                Bs[k][nq+4*j+1] = __uint_as_float(f2tf32(v.y));
                Bs[k][nq+4*j+2] = __uint_as_float(f2tf32(v.z));
                Bs[k][nq+4*j+3] = __uint_as_float(f2tf32(v.w));
            }
        }
        __syncthreads();
        #pragma unroll
        for (int ks = 0; ks < 8; ++ks) {
            int c0 = ks * 8 + ti;
            unsigned a0 = fu(As[wr*16+tg  ][c0  ]);
            unsigned a1 = fu(As[wr*16+tg+8][c0  ]);
            unsigned a2 = fu(As[wr*16+tg  ][c0+4]);
            unsigned a3 = fu(As[wr*16+tg+8][c0+4]);
            #pragma unroll
            for (int nt = 0; nt < 4; ++nt) {
                int bc = wc * 32 + nt * 8 + tg;
                unsigned b0 = fu(Bs[ks*8+ti  ][bc]);
                unsigned b1 = fu(Bs[ks*8+ti+4][bc]);
                asm volatile(
                    "mma.sync.aligned.m16n8k8.row.col.f32.tf32.tf32.f32 "
                    "{%0,%1,%2,%3}, {%4,%5,%6,%7}, {%8,%9}, {%0,%1,%2,%3};"
                    : "+f"(acc[nt][0]), "+f"(acc[nt][1]),
                      "+f"(acc[nt][2]), "+f"(acc[nt][3])
                    : "r"(a0), "r"(a1), "r"(a2), "r"(a3), "r"(b0), "r"(b1));
            }
        }
        __syncthreads();
    }
    #pragma unroll
    for (int nt = 0; nt < 4; ++nt) {
        int col = bn + wc * 32 + nt * 8 + 2 * ti;
        float bv0 = bias[col], bv1 = bias[col + 1];
        int r0 = bm + wr * 16 + tg, r1 = r0 + 8;
        if (r0 < M)
            *(float2*)(C + (size_t)r0 * N + col) =
                make_float2(fmaxf(acc[nt][0] + bv0, 0.f), fmaxf(acc[nt][1] + bv1, 0.f));
        if (r1 < M)
            *(float2*)(C + (size_t)r1 * N + col) =
                make_float2(fmaxf(acc[nt][2] + bv0, 0.f), fmaxf(acc[nt][3] + bv1, 0.f));
    }
}

// ---------------- GEMM B: BM=64, BN=128 (layer 2), 32x32 warp tiles -----------
__global__ __launch_bounds__(256) void gemm128(
    const float* __restrict__ A, const float* __restrict__ B,
    float* __restrict__ C, int M, int K, const float* __restrict__ bias)
{
    __shared__ float As[64][68];
    __shared__ float Bs[64][136];
    const int tid = threadIdx.x;
    const int bm = blockIdx.x * 64;
    const int wid = tid >> 5, l = tid & 31;
    const int wr = wid & 1;
    const int wc = wid >> 1;
    const int tg = l >> 2, ti = l & 3;

    float acc[2][4][4] = {};
    for (int kc = 0; kc < K; kc += 64) {
        {
            int row = tid >> 2, cq = (tid & 3) * 16;
            bool av = (bm + row) < M;
            const float* ap = A + (size_t)(bm + row) * K + kc + cq;
            #pragma unroll
            for (int j = 0; j < 4; ++j) {
                float4 v = av ? *(const float4*)(ap + 4 * j) : make_float4(0.f,0.f,0.f,0.f);
                As[row][cq+4*j+0] = __uint_as_float(f2tf32(v.x));
                As[row][cq+4*j+1] = __uint_as_float(f2tf32(v.y));
                As[row][cq+4*j+2] = __uint_as_float(f2tf32(v.z));
                As[row][cq+4*j+3] = __uint_as_float(f2tf32(v.w));
            }
        }
        {
            int k = tid >> 2, nq = (tid & 3) * 32;
            const float* bp = B + (size_t)(kc + k) * 128 + nq;
            #pragma unroll
            for (int j = 0; j < 8; ++j) {
                float4 v = *(const float4*)(bp + 4 * j);
                Bs[k][nq+4*j+0] = __uint_as_float(f2tf32(v.x));
                Bs[k][nq+4*j+1] = __uint_as_float(f2tf32(v.y));
                Bs[k][nq+4*j+2] = __uint_as_float(f2tf32(v.z));
                Bs[k][nq+4*j+3] = __uint_as_float(f2tf32(v.w));
            }
        }
        __syncthreads();
        #pragma unroll
        for (int ks = 0; ks < 8; ++ks) {
            int c0 = ks * 8 + ti;
            unsigned a[2][4];
            #pragma unroll
            for (int mt = 0; mt < 2; ++mt) {
                int r0 = wr * 32 + mt * 16 + tg;
                a[mt][0] = fu(As[r0  ][c0  ]);
                a[mt][1] = fu(As[r0+8][c0  ]);
                a[mt][2] = fu(As[r0  ][c0+4]);
                a[mt][3] = fu(As[r0+8][c0+4]);
            }
            #pragma unroll
            for (int nt = 0; nt < 4; ++nt) {
                int bc = wc * 32 + nt * 8 + tg;
                unsigned b0 = fu(Bs[ks*8+ti  ][bc]);
                unsigned b1 = fu(Bs[ks*8+ti+4][bc]);
                #pragma unroll
                for (int mt = 0; mt < 2; ++mt) {
                    asm volatile(
                        "mma.sync.aligned.m16n8k8.row.col.f32.tf32.tf32.f32 "
                        "{%0,%1,%2,%3}, {%4,%5,%6,%7}, {%8,%9}, {%0,%1,%2,%3};"
                        : "+f"(acc[mt][nt][0]), "+f"(acc[mt][nt][1]),
                          "+f"(acc[mt][nt][2]), "+f"(acc[mt][nt][3])
                        : "r"(a[mt][0]), "r"(a[mt][1]), "r"(a[mt][2]), "r"(a[mt][3]),
                          "r"(b0), "r"(b1));
                }
            }
        }
        __syncthreads();
    }
    #pragma unroll
    for (int mt = 0; mt < 2; ++mt) {
        #pragma unroll
        for (int nt = 0; nt < 4; ++nt) {
            int col = wc * 32 + nt * 8 + 2 * ti;
            float bv0 = bias[col], bv1 = bias[col + 1];
            int r0 = bm + wr * 32 + mt * 16 + tg, r1 = r0 + 8;
            if (r0 < M)
                *(float2*)(C + (size_t)r0 * 128 + col) =
                    make_float2(fmaxf(acc[mt][nt][0] + bv0, 0.f), fmaxf(acc[mt][nt][1] + bv1, 0.f));
            if (r1 < M)
                *(float2*)(C + (size_t)r1 * 128 + col) =
                    make_float2(fmaxf(acc[mt][nt][2] + bv0, 0.f), fmaxf(acc[mt][nt][3] + bv1, 0.f));
        }
    }
}

// ---------------- launch ------------------------------------------------------
extern "C" void kernel_launch(void* const* d_in, const int* in_sizes, int n_in,
                              void* d_out, int out_size) {
    const float* x      = (const float*)d_in[0];
    const int*   ei     = (const int*)  d_in[1];
    const float* pseudo = (const float*)d_in[2];
    const float* g1     = (const float*)d_in[3];
    const float* mu1    = (const float*)d_in[4];
    const float* sigma1 = (const float*)d_in[5];
    const float* root1  = (const float*)d_in[6];
    const float* b1     = (const float*)d_in[7];
    const float* g2     = (const float*)d_in[8];
    const float* mu2    = (const float*)d_in[9];
    const float* sigma2 = (const float*)d_in[10];
    const float* root2  = (const float*)d_in[11];
    const float* b2     = (const float*)d_in[12];
    const float* gs     = (const float*)d_in[13];
    const float* mus    = (const float*)d_in[14];
    const float* sigmas = (const float*)d_in[15];
    const float* roots  = (const float*)d_in[16];
    const float* bs     = (const float*)d_in[17];
    float* out = (float*)d_out;

    float *t1p, *t2p, *hp, *B1p, *B2p, *bias2p;
    cudaGetSymbolAddress((void**)&t1p, d_t1);
    cudaGetSymbolAddress((void**)&t2p, d_t2);
    cudaGetSymbolAddress((void**)&hp,  d_h);
    cudaGetSymbolAddress((void**)&B1p, d_B1);
    cudaGetSymbolAddress((void**)&B2p, d_B2);
    cudaGetSymbolAddress((void**)&bias2p, d_bias2);

    const int MT = (N_NODES + 63) / 64;
    const int EW = (N_EDGES + 255) / 256;
    const int NW = (N_NODES * 32 + 255) / 256;

    // CSR build + weight precompute (dst-sorted, dinv folded)
    zero_cnt<<<(N_NODES + 255) / 256, 256>>>();
    hist_dst<<<EW, 256>>>(ei);
    scan_deg<<<1, 1024>>>();
    bweave<<<(K2 * 128 + 255) / 256, 256>>>(g1, root1, g2, root2, gs, roots, b2, bs);
    scatterw<<<EW, 256>>>(ei, pseudo, mu1, sigma1, mu2, sigma2, mus, sigmas);

    // conv1
    tbuild1<<<NW, 256>>>(x);
    gemm64<<<dim3(1, MT), 256>>>(t1p, B1p, hp, N_NODES, 64, K1, b1);

    // conv2 + shortcut
    tbuild2<<<NW, 256>>>(x);
    gemm128<<<MT, 256>>>(t2p, B2p, out, N_NODES, K2, bias2p);
}

// round 6
// speedup vs baseline: 1.2481x; 1.2481x over previous
#include <cuda_runtime.h>
#include <math.h>

#define N_NODES 40962
#define N_EDGES 245760
#define KG 10
#define GMM_EPS 1e-15f
#define K1 704      // 640 (agg1) + 64 (x row -> root1)
#define K2 1408     // 640 (agg2) + 64 (h) + 640 (aggs) + 64 (x)

// ---------------- scratch (device globals; no runtime allocation) -------------
__device__ int   d_cnt[N_NODES];
__device__ int   d_cur[N_NODES];
__device__ int   d_offs[N_NODES + 1];
__device__ float d_dinv[N_NODES];
__device__ int2  d_se[N_EDGES];                  // (src, orig edge id), dst-sorted
__device__ float d_t1[(size_t)N_NODES * K1];
__device__ float d_t2[(size_t)N_NODES * K2];
__device__ float d_h [(size_t)N_NODES * 64];
__device__ float d_B1[K1 * 64];
__device__ float d_B2[K2 * 128];
__device__ float d_bias2[128];

// ---------------- prep kernels ------------------------------------------------
__global__ void zero_cnt() {
    int i = blockIdx.x * blockDim.x + threadIdx.x;
    if (i < N_NODES) { d_cnt[i] = 0; d_cur[i] = 0; }
}

__global__ void hist_dst(const int* __restrict__ ei) {
    int e = blockIdx.x * blockDim.x + threadIdx.x;
    if (e < N_EDGES) atomicAdd(&d_cnt[ei[N_EDGES + e]], 1);
}

// single-block exclusive scan (R3 version: multi-phase, no register spills)
__global__ void scan_deg() {
    __shared__ int sh[32];
    __shared__ int carry;
    int t = threadIdx.x, lane = t & 31, wid = t >> 5;
    if (t == 0) { carry = 0; d_offs[0] = 0; }
    __syncthreads();
    for (int base = 0; base < N_NODES; base += 1024) {
        int i = base + t;
        int v = (i < N_NODES) ? d_cnt[i] : 0;
        if (i < N_NODES) d_dinv[i] = 1.0f / (float)max(v, 1);
        int s = v;
        #pragma unroll
        for (int off = 1; off < 32; off <<= 1) {
            int n = __shfl_up_sync(0xffffffffu, s, off);
            if (lane >= off) s += n;
        }
        if (lane == 31) sh[wid] = s;
        __syncthreads();
        if (wid == 0) {
            int w = sh[lane];
            #pragma unroll
            for (int off = 1; off < 32; off <<= 1) {
                int n = __shfl_up_sync(0xffffffffu, w, off);
                if (lane >= off) w += n;
            }
            sh[lane] = w;
        }
        __syncthreads();
        int incl = s + (wid > 0 ? sh[wid - 1] : 0);
        int cbase = carry;
        if (i < N_NODES) d_offs[i + 1] = cbase + incl;
        __syncthreads();
        if (t == 1023) carry = cbase + incl;
        __syncthreads();
    }
}

// weave both big B matrices + combined bias
__global__ void bweave(const float* __restrict__ g1, const float* __restrict__ root1,
                       const float* __restrict__ g2, const float* __restrict__ root2,
                       const float* __restrict__ gs, const float* __restrict__ roots,
                       const float* __restrict__ b2, const float* __restrict__ bs) {
    int idx = blockIdx.x * blockDim.x + threadIdx.x;
    if (idx < 128) d_bias2[idx] = b2[idx] + bs[idx];
    if (idx < K1 * 64) {
        int r = idx >> 6, c = idx & 63;
        float v;
        if (r < 640) { int k = r >> 6, cin = r & 63; v = g1[cin * 640 + k * 64 + c]; }
        else         { v = root1[(r - 640) * 64 + c]; }
        d_B1[idx] = v;
    }
    if (idx < K2 * 128) {
        int r = idx >> 7, c = idx & 127;
        float v;
        if (r < 640)       { int k = r >> 6, cin = r & 63; v = g2[cin * 1280 + k * 128 + c]; }
        else if (r < 704)  { v = root2[(r - 640) * 128 + c]; }
        else if (r < 1344) { int rr = r - 704; int k = rr >> 6, cin = rr & 63; v = gs[cin * 1280 + k * 128 + c]; }
        else               { v = roots[(r - 1344) * 128 + c]; }
        d_B2[idx] = v;
    }
}

// dst-sort scatter: just (src, edge-id)
__global__ void scatter_idx(const int* __restrict__ ei) {
    int e = blockIdx.x * blockDim.x + threadIdx.x;
    if (e >= N_EDGES) return;
    int src = ei[e];
    int dst = ei[N_EDGES + e];
    int pos = d_offs[dst] + atomicAdd(&d_cur[dst], 1);
    d_se[pos] = make_int2(src, e);
}

// ---------------- t-builds (warp per dst node, inline gaussians) --------------
__global__ __launch_bounds__(256) void tbuild1(
    const float* __restrict__ x, const float* __restrict__ pseudo,
    const float* __restrict__ mu, const float* __restrict__ sg)
{
    int gw = (blockIdx.x * blockDim.x + threadIdx.x) >> 5;
    int lane = threadIdx.x & 31;
    if (gw >= N_NODES) return;

    float m0 = 0.f, m1 = 0.f, i0 = 0.f, i1 = 0.f;
    if (lane < KG) {
        m0 = mu[2 * lane]; m1 = mu[2 * lane + 1];
        float s0 = sg[2 * lane], s1 = sg[2 * lane + 1];
        i0 = -0.5f / (GMM_EPS + s0 * s0);
        i1 = -0.5f / (GMM_EPS + s1 * s1);
    }

    int beg = d_offs[gw], end = d_offs[gw + 1];
    float dinv = d_dinv[gw];
    float a[KG][2];
    #pragma unroll
    for (int k = 0; k < KG; ++k) { a[k][0] = 0.f; a[k][1] = 0.f; }

    int2 se_next = (beg < end) ? d_se[beg] : make_int2(0, 0);
    for (int e = beg; e < end; ++e) {
        int2 se = se_next;
        if (e + 1 < end) se_next = d_se[e + 1];
        float2 p = ((const float2*)pseudo)[se.y];
        float wv = 0.f;
        if (lane < KG) {
            float dx = p.x - m0, dy = p.y - m1;
            wv = __expf(dx * dx * i0 + dy * dy * i1);
        }
        float x0 = x[(size_t)se.x * 64 + lane];
        float x1 = x[(size_t)se.x * 64 + 32 + lane];
        #pragma unroll
        for (int k = 0; k < KG; ++k) {
            float w = __shfl_sync(0xffffffffu, wv, k);
            a[k][0] = fmaf(w, x0, a[k][0]);
            a[k][1] = fmaf(w, x1, a[k][1]);
        }
    }
    float* tr = d_t1 + (size_t)gw * K1;
    #pragma unroll
    for (int k = 0; k < KG; ++k) {
        tr[k * 64 + lane]      = a[k][0] * dinv;
        tr[k * 64 + 32 + lane] = a[k][1] * dinv;
    }
    tr[640 + lane]      = x[(size_t)gw * 64 + lane];
    tr[640 + 32 + lane] = x[(size_t)gw * 64 + 32 + lane];
}

__global__ __launch_bounds__(256) void tbuild2(
    const float* __restrict__ x, const float* __restrict__ pseudo,
    const float* __restrict__ mu2, const float* __restrict__ sg2,
    const float* __restrict__ mus, const float* __restrict__ sgs)
{
    int gw = (blockIdx.x * blockDim.x + threadIdx.x) >> 5;
    int lane = threadIdx.x & 31;
    if (gw >= N_NODES) return;

    float m0 = 0.f, m1 = 0.f, i0 = 0.f, i1 = 0.f;
    if (lane < KG) {
        m0 = mu2[2 * lane]; m1 = mu2[2 * lane + 1];
        float s0 = sg2[2 * lane], s1 = sg2[2 * lane + 1];
        i0 = -0.5f / (GMM_EPS + s0 * s0);
        i1 = -0.5f / (GMM_EPS + s1 * s1);
    } else if (lane < 2 * KG) {
        int k = lane - KG;
        m0 = mus[2 * k]; m1 = mus[2 * k + 1];
        float s0 = sgs[2 * k], s1 = sgs[2 * k + 1];
        i0 = -0.5f / (GMM_EPS + s0 * s0);
        i1 = -0.5f / (GMM_EPS + s1 * s1);
    }

    int beg = d_offs[gw], end = d_offs[gw + 1];
    float dinv = d_dinv[gw];
    float a2[KG][2], as_[KG][2];
    #pragma unroll
    for (int k = 0; k < KG; ++k) { a2[k][0]=0.f; a2[k][1]=0.f; as_[k][0]=0.f; as_[k][1]=0.f; }

    int2 se_next = (beg < end) ? d_se[beg] : make_int2(0, 0);
    for (int e = beg; e < end; ++e) {
        int2 se = se_next;
        if (e + 1 < end) se_next = d_se[e + 1];
        float2 p = ((const float2*)pseudo)[se.y];
        float wv = 0.f;
        if (lane < 2 * KG) {
            float dx = p.x - m0, dy = p.y - m1;
            wv = __expf(dx * dx * i0 + dy * dy * i1);
        }
        float h0 = d_h[(size_t)se.x * 64 + lane];
        float h1 = d_h[(size_t)se.x * 64 + 32 + lane];
        float x0 = x[(size_t)se.x * 64 + lane];
        float x1 = x[(size_t)se.x * 64 + 32 + lane];
        #pragma unroll
        for (int k = 0; k < KG; ++k) {
            float w2 = __shfl_sync(0xffffffffu, wv, k);
            float ws = __shfl_sync(0xffffffffu, wv, KG + k);
            a2[k][0]  = fmaf(w2, h0, a2[k][0]);
            a2[k][1]  = fmaf(w2, h1, a2[k][1]);
            as_[k][0] = fmaf(ws, x0, as_[k][0]);
            as_[k][1] = fmaf(ws, x1, as_[k][1]);
        }
    }
    float* tr = d_t2 + (size_t)gw * K2;
    #pragma unroll
    for (int k = 0; k < KG; ++k) {
        tr[k * 64 + lane]            = a2[k][0] * dinv;
        tr[k * 64 + 32 + lane]       = a2[k][1] * dinv;
        tr[704 + k * 64 + lane]      = as_[k][0] * dinv;
        tr[704 + k * 64 + 32 + lane] = as_[k][1] * dinv;
    }
    tr[640 + lane]       = d_h[(size_t)gw * 64 + lane];
    tr[640 + 32 + lane]  = d_h[(size_t)gw * 64 + 32 + lane];
    tr[1344 + lane]      = x[(size_t)gw * 64 + lane];
    tr[1344 + 32 + lane] = x[(size_t)gw * 64 + 32 + lane];
}

// ---------------- tf32 tensor-core GEMM (R3 gemm_big, 64x64 tiles) ------------
__device__ __forceinline__ unsigned f2tf32(float x) {
    unsigned r;
    asm("cvt.rna.tf32.f32 %0, %1;" : "=r"(r) : "f"(x));
    return r;
}
__device__ __forceinline__ unsigned fu(float x) { return __float_as_uint(x); }

__global__ __launch_bounds__(256) void gemm_big(
    const float* __restrict__ A, const float* __restrict__ B,
    float* __restrict__ C, int M, int N, int K, const float* __restrict__ bias)
{
    __shared__ float As[64][68];
    __shared__ float Bs[64][72];
    const int tid = threadIdx.x;
    const int bm = blockIdx.y * 64;
    const int bn = blockIdx.x * 64;
    const int wid = tid >> 5, l = tid & 31;
    const int wr = wid & 3, wc = wid >> 2;
    const int tg = l >> 2, ti = l & 3;

    float acc[4][4] = {};
    for (int kc = 0; kc < K; kc += 64) {
        {
            int row = tid >> 2, cq = (tid & 3) * 16;
            bool av = (bm + row) < M;
            const float* ap = A + (size_t)(bm + row) * K + kc + cq;
            #pragma unroll
            for (int j = 0; j < 4; ++j) {
                float4 v = av ? *(const float4*)(ap + 4 * j) : make_float4(0.f,0.f,0.f,0.f);
                As[row][cq+4*j+0] = __uint_as_float(f2tf32(v.x));
                As[row][cq+4*j+1] = __uint_as_float(f2tf32(v.y));
                As[row][cq+4*j+2] = __uint_as_float(f2tf32(v.z));
                As[row][cq+4*j+3] = __uint_as_float(f2tf32(v.w));
            }
        }
        {
            int k = tid >> 2, nq = (tid & 3) * 16;
            const float* bp = B + (size_t)(kc + k) * N + bn + nq;
            #pragma unroll
            for (int j = 0; j < 4; ++j) {
                float4 v = *(const float4*)(bp + 4 * j);
                Bs[k][nq+4*j+0] = __uint_as_float(f2tf32(v.x));
                Bs[k][nq+4*j+1] = __uint_as_float(f2tf32(v.y));
                Bs[k][nq+4*j+2] = __uint_as_float(f2tf32(v.z));
                Bs[k][nq+4*j+3] = __uint_as_float(f2tf32(v.w));
            }
        }
        __syncthreads();
        #pragma unroll
        for (int ks = 0; ks < 8; ++ks) {
            int c0 = ks * 8 + ti;
            unsigned a0 = fu(As[wr*16+tg  ][c0  ]);
            unsigned a1 = fu(As[wr*16+tg+8][c0  ]);
            unsigned a2 = fu(As[wr*16+tg  ][c0+4]);
            unsigned a3 = fu(As[wr*16+tg+8][c0+4]);
            #pragma unroll
            for (int nt = 0; nt < 4; ++nt) {
                int bc = wc * 32 + nt * 8 + tg;
                unsigned b0 = fu(Bs[ks*8+ti  ][bc]);
                unsigned b1 = fu(Bs[ks*8+ti+4][bc]);
                asm volatile(
                    "mma.sync.aligned.m16n8k8.row.col.f32.tf32.tf32.f32 "
                    "{%0,%1,%2,%3}, {%4,%5,%6,%7}, {%8,%9}, {%0,%1,%2,%3};"
                    : "+f"(acc[nt][0]), "+f"(acc[nt][1]),
                      "+f"(acc[nt][2]), "+f"(acc[nt][3])
                    : "r"(a0), "r"(a1), "r"(a2), "r"(a3), "r"(b0), "r"(b1));
            }
        }
        __syncthreads();
    }
    #pragma unroll
    for (int nt = 0; nt < 4; ++nt) {
        int col = bn + wc * 32 + nt * 8 + 2 * ti;
        float bv0 = bias[col], bv1 = bias[col + 1];
        int r0 = bm + wr * 16 + tg, r1 = r0 + 8;
        if (r0 < M)
            *(float2*)(C + (size_t)r0 * N + col) =
                make_float2(fmaxf(acc[nt][0] + bv0, 0.f), fmaxf(acc[nt][1] + bv1, 0.f));
        if (r1 < M)
            *(float2*)(C + (size_t)r1 * N + col) =
                make_float2(fmaxf(acc[nt][2] + bv0, 0.f), fmaxf(acc[nt][3] + bv1, 0.f));
    }
}

// ---------------- launch ------------------------------------------------------
extern "C" void kernel_launch(void* const* d_in, const int* in_sizes, int n_in,
                              void* d_out, int out_size) {
    const float* x      = (const float*)d_in[0];
    const int*   ei     = (const int*)  d_in[1];
    const float* pseudo = (const float*)d_in[2];
    const float* g1     = (const float*)d_in[3];
    const float* mu1    = (const float*)d_in[4];
    const float* sigma1 = (const float*)d_in[5];
    const float* root1  = (const float*)d_in[6];
    const float* b1     = (const float*)d_in[7];
    const float* g2     = (const float*)d_in[8];
    const float* mu2    = (const float*)d_in[9];
    const float* sigma2 = (const float*)d_in[10];
    const float* root2  = (const float*)d_in[11];
    const float* b2     = (const float*)d_in[12];
    const float* gs     = (const float*)d_in[13];
    const float* mus    = (const float*)d_in[14];
    const float* sigmas = (const float*)d_in[15];
    const float* roots  = (const float*)d_in[16];
    const float* bs     = (const float*)d_in[17];
    float* out = (float*)d_out;

    float *t1p, *t2p, *hp, *B1p, *B2p, *bias2p;
    cudaGetSymbolAddress((void**)&t1p, d_t1);
    cudaGetSymbolAddress((void**)&t2p, d_t2);
    cudaGetSymbolAddress((void**)&hp,  d_h);
    cudaGetSymbolAddress((void**)&B1p, d_B1);
    cudaGetSymbolAddress((void**)&B2p, d_B2);
    cudaGetSymbolAddress((void**)&bias2p, d_bias2);

    const int MT = (N_NODES + 63) / 64;
    const int EW = (N_EDGES + 255) / 256;
    const int NW = (N_NODES * 32 + 255) / 256;

    // CSR build
    zero_cnt<<<(N_NODES + 255) / 256, 256>>>();
    hist_dst<<<EW, 256>>>(ei);
    scan_deg<<<1, 1024>>>();
    bweave<<<(K2 * 128 + 255) / 256, 256>>>(g1, root1, g2, root2, gs, roots, b2, bs);
    scatter_idx<<<EW, 256>>>(ei);

    // conv1: t1 = [mean-agg(x) | x], h = relu(t1 @ B1 + b1)
    tbuild1<<<NW, 256>>>(x, pseudo, mu1, sigma1);
    gemm_big<<<dim3(1, MT), 256>>>(t1p, B1p, hp, N_NODES, 64, K1, b1);

    // conv2 + shortcut: t2 = [agg(h) | h | agg(x) | x], out = relu(t2 @ B2 + bias)
    tbuild2<<<NW, 256>>>(x, pseudo, mu2, sigma2, mus, sigmas);
    gemm_big<<<dim3(2, MT), 256>>>(t2p, B2p, out, N_NODES, 128, K2, bias2p);
}

// round 7
// speedup vs baseline: 2.3989x; 1.9220x over previous
#include <cuda_runtime.h>
#include <cuda_fp16.h>
#include <math.h>

#define N_NODES 40962
#define N_EDGES 245760
#define KG 10
#define GMM_EPS 1e-15f
#define K1 704      // 640 (agg1) + 64 (x row -> root1)
#define K2 1408     // 640 (agg2) + 64 (h) + 640 (aggs) + 64 (x)
#define NB 161      // scan blocks: ceil(40962/256)

// ---------------- scratch (device globals; no runtime allocation) -------------
__device__ int    d_cnt[N_NODES];
__device__ int    d_cur[N_NODES];
__device__ int    d_offs[N_NODES + 1];
__device__ float  d_dinv[N_NODES];
__device__ int    d_bsum[NB];
__device__ int    d_boff[NB];
__device__ int2   d_se[N_EDGES];                     // (src, orig edge id), dst-sorted
__device__ __half2 d_t1h[(size_t)N_NODES * (K1 / 2)];
__device__ __half2 d_t2h[(size_t)N_NODES * (K2 / 2)];
__device__ float  d_h [(size_t)N_NODES * 64];
__device__ __half d_B1h[64 * K1];                    // [n][k] transposed
__device__ __half d_B2h[128 * K2];                   // [n][k] transposed
__device__ float  d_bias2[128];

// ---------------- prep kernels ------------------------------------------------
__global__ void zero_cnt() {
    int i = blockIdx.x * blockDim.x + threadIdx.x;
    if (i < N_NODES) { d_cnt[i] = 0; d_cur[i] = 0; }
}

__global__ void hist_dst(const int* __restrict__ ei) {
    int e = blockIdx.x * blockDim.x + threadIdx.x;
    if (e < N_EDGES) atomicAdd(&d_cnt[ei[N_EDGES + e]], 1);
}

// --- hierarchical scan: block sums -> top scan -> rescan with offsets ---------
__global__ void scan_blk() {
    __shared__ int ws[8];
    int i = blockIdx.x * 256 + threadIdx.x;
    int v = (i < N_NODES) ? d_cnt[i] : 0;
    int lane = threadIdx.x & 31, w = threadIdx.x >> 5;
    int s = v;
    #pragma unroll
    for (int o = 16; o; o >>= 1) s += __shfl_xor_sync(0xffffffffu, s, o);
    if (lane == 0) ws[w] = s;
    __syncthreads();
    if (threadIdx.x == 0) {
        int t = 0;
        #pragma unroll
        for (int j = 0; j < 8; ++j) t += ws[j];
        d_bsum[blockIdx.x] = t;
    }
}

__global__ void scan_top() {
    __shared__ int sh[8];
    int t = threadIdx.x, lane = t & 31, w = t >> 5;
    int v = (t < NB) ? d_bsum[t] : 0;
    int s = v;
    #pragma unroll
    for (int o = 1; o < 32; o <<= 1) {
        int n = __shfl_up_sync(0xffffffffu, s, o);
        if (lane >= o) s += n;
    }
    if (lane == 31) sh[w] = s;
    __syncthreads();
    if (w == 0 && lane < 8) {
        int x = sh[lane];
        #pragma unroll
        for (int o = 1; o < 8; o <<= 1) {
            int n = __shfl_up_sync(0xffu, x, o);
            if (lane >= o) x += n;
        }
        sh[lane] = x;
    }
    __syncthreads();
    int excl = s - v + (w > 0 ? sh[w - 1] : 0);
    if (t < NB) d_boff[t] = excl;
    if (t == 0) d_offs[N_NODES] = N_EDGES;
}

__global__ void scan_fin() {
    __shared__ int sh[8];
    int t = threadIdx.x, lane = t & 31, w = t >> 5;
    int i = blockIdx.x * 256 + t;
    int v = (i < N_NODES) ? d_cnt[i] : 0;
    int s = v;
    #pragma unroll
    for (int o = 1; o < 32; o <<= 1) {
        int n = __shfl_up_sync(0xffffffffu, s, o);
        if (lane >= o) s += n;
    }
    if (lane == 31) sh[w] = s;
    __syncthreads();
    if (w == 0 && lane < 8) {
        int x = sh[lane];
        #pragma unroll
        for (int o = 1; o < 8; o <<= 1) {
            int n = __shfl_up_sync(0xffu, x, o);
            if (lane >= o) x += n;
        }
        sh[lane] = x;
    }
    __syncthreads();
    int excl = s - v + (w > 0 ? sh[w - 1] : 0);
    if (i < N_NODES) {
        d_offs[i] = d_boff[blockIdx.x] + excl;
        d_dinv[i] = 1.0f / (float)max(v, 1);
    }
}

// weave big B matrices (transposed to [n][k], half) + combined bias
__global__ void bweave(const float* __restrict__ g1, const float* __restrict__ root1,
                       const float* __restrict__ g2, const float* __restrict__ root2,
                       const float* __restrict__ gs, const float* __restrict__ roots,
                       const float* __restrict__ b2, const float* __restrict__ bs) {
    int idx = blockIdx.x * blockDim.x + threadIdx.x;
    if (idx < 128) d_bias2[idx] = b2[idx] + bs[idx];
    if (idx < 64 * K1) {
        int n = idx / K1, k = idx % K1;
        float v;
        if (k < 640) v = g1[(k & 63) * 640 + (k >> 6) * 64 + n];
        else         v = root1[(k - 640) * 64 + n];
        d_B1h[idx] = __float2half_rn(v);
    }
    if (idx < 128 * K2) {
        int n = idx / K2, k = idx % K2;
        float v;
        if (k < 640)       v = g2[(k & 63) * 1280 + (k >> 6) * 128 + n];
        else if (k < 704)  v = root2[(k - 640) * 128 + n];
        else if (k < 1344) { int kk = k - 704; v = gs[(kk & 63) * 1280 + (kk >> 6) * 128 + n]; }
        else               v = roots[(k - 1344) * 128 + n];
        d_B2h[idx] = __float2half_rn(v);
    }
}

// dst-sort scatter: (src, edge-id)
__global__ void scatter_idx(const int* __restrict__ ei) {
    int e = blockIdx.x * blockDim.x + threadIdx.x;
    if (e >= N_EDGES) return;
    int src = ei[e];
    int dst = ei[N_EDGES + e];
    int pos = d_offs[dst] + atomicAdd(&d_cur[dst], 1);
    d_se[pos] = make_int2(src, e);
}

// ---------------- t-builds (warp per dst node; lane owns channels 2l,2l+1) ----
__global__ __launch_bounds__(256) void tbuild1(
    const float* __restrict__ x, const float* __restrict__ pseudo,
    const float* __restrict__ mu, const float* __restrict__ sg)
{
    int gw = (blockIdx.x * blockDim.x + threadIdx.x) >> 5;
    int lane = threadIdx.x & 31;
    if (gw >= N_NODES) return;

    float m0 = 0.f, m1 = 0.f, i0 = 0.f, i1 = 0.f;
    if (lane < KG) {
        m0 = mu[2 * lane]; m1 = mu[2 * lane + 1];
        float s0 = sg[2 * lane], s1 = sg[2 * lane + 1];
        i0 = -0.5f / (GMM_EPS + s0 * s0);
        i1 = -0.5f / (GMM_EPS + s1 * s1);
    }

    const float2* x2 = (const float2*)x;
    int beg = d_offs[gw], end = d_offs[gw + 1];
    float dinv = d_dinv[gw];
    float2 a[KG];
    #pragma unroll
    for (int k = 0; k < KG; ++k) a[k] = make_float2(0.f, 0.f);

    int2 se_next = (beg < end) ? d_se[beg] : make_int2(0, 0);
    for (int e = beg; e < end; ++e) {
        int2 se = se_next;
        if (e + 1 < end) se_next = d_se[e + 1];
        float2 p = ((const float2*)pseudo)[se.y];
        float wv = 0.f;
        if (lane < KG) {
            float dx = p.x - m0, dy = p.y - m1;
            wv = __expf(dx * dx * i0 + dy * dy * i1);
        }
        float2 xo = x2[(size_t)se.x * 32 + lane];
        #pragma unroll
        for (int k = 0; k < KG; ++k) {
            float w = __shfl_sync(0xffffffffu, wv, k);
            a[k].x = fmaf(w, xo.x, a[k].x);
            a[k].y = fmaf(w, xo.y, a[k].y);
        }
    }
    __half2* tr = d_t1h + (size_t)gw * (K1 / 2);
    #pragma unroll
    for (int k = 0; k < KG; ++k)
        tr[k * 32 + lane] = __floats2half2_rn(a[k].x * dinv, a[k].y * dinv);
    float2 own = x2[(size_t)gw * 32 + lane];
    tr[320 + lane] = __floats2half2_rn(own.x, own.y);
}

__global__ __launch_bounds__(256) void tbuild2(
    const float* __restrict__ x, const float* __restrict__ pseudo,
    const float* __restrict__ mu2, const float* __restrict__ sg2,
    const float* __restrict__ mus, const float* __restrict__ sgs)
{
    int gw = (blockIdx.x * blockDim.x + threadIdx.x) >> 5;
    int lane = threadIdx.x & 31;
    if (gw >= N_NODES) return;

    float m0 = 0.f, m1 = 0.f, i0 = 0.f, i1 = 0.f;
    if (lane < KG) {
        m0 = mu2[2 * lane]; m1 = mu2[2 * lane + 1];
        float s0 = sg2[2 * lane], s1 = sg2[2 * lane + 1];
        i0 = -0.5f / (GMM_EPS + s0 * s0);
        i1 = -0.5f / (GMM_EPS + s1 * s1);
    } else if (lane < 2 * KG) {
        int k = lane - KG;
        m0 = mus[2 * k]; m1 = mus[2 * k + 1];
        float s0 = sgs[2 * k], s1 = sgs[2 * k + 1];
        i0 = -0.5f / (GMM_EPS + s0 * s0);
        i1 = -0.5f / (GMM_EPS + s1 * s1);
    }

    const float2* x2 = (const float2*)x;
    const float2* h2 = (const float2*)d_h;
    int beg = d_offs[gw], end = d_offs[gw + 1];
    float dinv = d_dinv[gw];
    float2 a2[KG], as_[KG];
    #pragma unroll
    for (int k = 0; k < KG; ++k) { a2[k] = make_float2(0.f, 0.f); as_[k] = make_float2(0.f, 0.f); }

    int2 se_next = (beg < end) ? d_se[beg] : make_int2(0, 0);
    for (int e = beg; e < end; ++e) {
        int2 se = se_next;
        if (e + 1 < end) se_next = d_se[e + 1];
        float2 p = ((const float2*)pseudo)[se.y];
        float wv = 0.f;
        if (lane < 2 * KG) {
            float dx = p.x - m0, dy = p.y - m1;
            wv = __expf(dx * dx * i0 + dy * dy * i1);
        }
        float2 ho = h2[(size_t)se.x * 32 + lane];
        float2 xo = x2[(size_t)se.x * 32 + lane];
        #pragma unroll
        for (int k = 0; k < KG; ++k) {
            float w2 = __shfl_sync(0xffffffffu, wv, k);
            float ws = __shfl_sync(0xffffffffu, wv, KG + k);
            a2[k].x  = fmaf(w2, ho.x, a2[k].x);
            a2[k].y  = fmaf(w2, ho.y, a2[k].y);
            as_[k].x = fmaf(ws, xo.x, as_[k].x);
            as_[k].y = fmaf(ws, xo.y, as_[k].y);
        }
    }
    __half2* tr = d_t2h + (size_t)gw * (K2 / 2);
    #pragma unroll
    for (int k = 0; k < KG; ++k) {
        tr[k * 32 + lane]       = __floats2half2_rn(a2[k].x * dinv, a2[k].y * dinv);
        tr[352 + k * 32 + lane] = __floats2half2_rn(as_[k].x * dinv, as_[k].y * dinv);
    }
    float2 hown = h2[(size_t)gw * 32 + lane];
    float2 xown = x2[(size_t)gw * 32 + lane];
    tr[320 + lane] = __floats2half2_rn(hown.x, hown.y);
    tr[672 + lane] = __floats2half2_rn(xown.x, xown.y);
}

// ---------------- fp16 tensor-core GEMM: BM=BN=64, m16n8k16 -------------------
// C[M,N] = relu(A[M,K] @ Bt[N,K]^T + bias). A half row-major, Bt half [n][k].
__global__ __launch_bounds__(256) void gemm_h(
    const __half* __restrict__ A, const __half* __restrict__ Bt,
    float* __restrict__ C, int M, int N, int K, const float* __restrict__ bias)
{
    __shared__ __align__(16) __half As[64][72];
    __shared__ __align__(16) __half Bs[64][72];
    const int tid = threadIdx.x;
    const int bm = blockIdx.y * 64;
    const int bn = blockIdx.x * 64;
    const int wid = tid >> 5, l = tid & 31;
    const int wr = wid & 3, wc = wid >> 2;     // 4 m-warps x 2 n-warps
    const int tg = l >> 2, ti = l & 3;

    const int row = tid >> 2, q = tid & 3;     // loader role: 4 threads/row, 32B each

    float acc[4][4] = {};
    for (int kc = 0; kc < K; kc += 64) {
        // A tile: 64 rows x 64 halves
        {
            bool av = (bm + row) < M;
            const __half* ap = A + (size_t)(bm + row) * K + kc + q * 16;
            uint4 v0 = av ? *(const uint4*)(ap)     : make_uint4(0, 0, 0, 0);
            uint4 v1 = av ? *(const uint4*)(ap + 8) : make_uint4(0, 0, 0, 0);
            *(uint4*)&As[row][q * 16]     = v0;
            *(uint4*)&As[row][q * 16 + 8] = v1;
        }
        // B tile: rows bn..bn+63 of Bt, 64 halves of k
        {
            const __half* bp = Bt + (size_t)(bn + row) * K + kc + q * 16;
            uint4 v0 = *(const uint4*)(bp);
            uint4 v1 = *(const uint4*)(bp + 8);
            *(uint4*)&Bs[row][q * 16]     = v0;
            *(uint4*)&Bs[row][q * 16 + 8] = v1;
        }
        __syncthreads();
        #pragma unroll
        for (int ks = 0; ks < 4; ++ks) {
            int kb = ks * 16 + 2 * ti;
            unsigned a0 = *(const unsigned*)&As[wr * 16 + tg    ][kb    ];
            unsigned a1 = *(const unsigned*)&As[wr * 16 + tg + 8][kb    ];
            unsigned a2 = *(const unsigned*)&As[wr * 16 + tg    ][kb + 8];
            unsigned a3 = *(const unsigned*)&As[wr * 16 + tg + 8][kb + 8];
            #pragma unroll
            for (int nt = 0; nt < 4; ++nt) {
                int bc = wc * 32 + nt * 8 + tg;
                unsigned b0 = *(const unsigned*)&Bs[bc][kb    ];
                unsigned b1 = *(const unsigned*)&Bs[bc][kb + 8];
                asm volatile(
                    "mma.sync.aligned.m16n8k16.row.col.f32.f16.f16.f32 "
                    "{%0,%1,%2,%3}, {%4,%5,%6,%7}, {%8,%9}, {%0,%1,%2,%3};"
                    : "+f"(acc[nt][0]), "+f"(acc[nt][1]),
                      "+f"(acc[nt][2]), "+f"(acc[nt][3])
                    : "r"(a0), "r"(a1), "r"(a2), "r"(a3), "r"(b0), "r"(b1));
            }
        }
        __syncthreads();
    }
    #pragma unroll
    for (int nt = 0; nt < 4; ++nt) {
        int col = bn + wc * 32 + nt * 8 + 2 * ti;
        float bv0 = bias[col], bv1 = bias[col + 1];
        int r0 = bm + wr * 16 + tg, r1 = r0 + 8;
        if (r0 < M)
            *(float2*)(C + (size_t)r0 * N + col) =
                make_float2(fmaxf(acc[nt][0] + bv0, 0.f), fmaxf(acc[nt][1] + bv1, 0.f));
        if (r1 < M)
            *(float2*)(C + (size_t)r1 * N + col) =
                make_float2(fmaxf(acc[nt][2] + bv0, 0.f), fmaxf(acc[nt][3] + bv1, 0.f));
    }
}

// ---------------- launch ------------------------------------------------------
extern "C" void kernel_launch(void* const* d_in, const int* in_sizes, int n_in,
                              void* d_out, int out_size) {
    const float* x      = (const float*)d_in[0];
    const int*   ei     = (const int*)  d_in[1];
    const float* pseudo = (const float*)d_in[2];
    const float* g1     = (const float*)d_in[3];
    const float* mu1    = (const float*)d_in[4];
    const float* sigma1 = (const float*)d_in[5];
    const float* root1  = (const float*)d_in[6];
    const float* b1     = (const float*)d_in[7];
    const float* g2     = (const float*)d_in[8];
    const float* mu2    = (const float*)d_in[9];
    const float* sigma2 = (const float*)d_in[10];
    const float* root2  = (const float*)d_in[11];
    const float* b2     = (const float*)d_in[12];
    const float* gs     = (const float*)d_in[13];
    const float* mus    = (const float*)d_in[14];
    const float* sigmas = (const float*)d_in[15];
    const float* roots  = (const float*)d_in[16];
    const float* bs     = (const float*)d_in[17];
    float* out = (float*)d_out;

    __half *t1p, *t2p, *B1p, *B2p;
    float *hp, *bias2p;
    cudaGetSymbolAddress((void**)&t1p, d_t1h);
    cudaGetSymbolAddress((void**)&t2p, d_t2h);
    cudaGetSymbolAddress((void**)&hp,  d_h);
    cudaGetSymbolAddress((void**)&B1p, d_B1h);
    cudaGetSymbolAddress((void**)&B2p, d_B2h);
    cudaGetSymbolAddress((void**)&bias2p, d_bias2);

    const int MT = (N_NODES + 63) / 64;
    const int EW = (N_EDGES + 255) / 256;
    const int NW = (N_NODES * 32 + 255) / 256;

    // CSR build (parallel scan) + weight weave
    zero_cnt<<<(N_NODES + 255) / 256, 256>>>();
    hist_dst<<<EW, 256>>>(ei);
    scan_blk<<<NB, 256>>>();
    scan_top<<<1, 256>>>();
    scan_fin<<<NB, 256>>>();
    bweave<<<(128 * K2 + 255) / 256, 256>>>(g1, root1, g2, root2, gs, roots, b2, bs);
    scatter_idx<<<EW, 256>>>(ei);

    // conv1: t1 = [mean-agg(x) | x], h = relu(t1 @ B1 + b1)
    tbuild1<<<NW, 256>>>(x, pseudo, mu1, sigma1);
    gemm_h<<<dim3(1, MT), 256>>>(t1p, B1p, hp, N_NODES, 64, K1, b1);

    // conv2 + shortcut: t2 = [agg(h) | h | agg(x) | x], out = relu(t2 @ B2 + bias)
    tbuild2<<<NW, 256>>>(x, pseudo, mu2, sigma2, mus, sigmas);
    gemm_h<<<dim3(2, MT), 256>>>(t2p, B2p, out, N_NODES, 128, K2, bias2p);
}

// round 8
// speedup vs baseline: 2.7738x; 1.1563x over previous
#include <cuda_runtime.h>
#include <cuda_fp16.h>
#include <math.h>

#define N_NODES 40962
#define N_EDGES 245760
#define KG 10
#define GMM_EPS 1e-15f
#define K1 704      // 640 (agg1) + 64 (x row -> root1)
#define K2 1408     // 640 (agg2) + 64 (h) + 640 (aggs) + 64 (x)
#define NB 161      // scan blocks: ceil(40962/256)

// ---------------- scratch (device globals; no runtime allocation) -------------
__device__ int    d_cnt[N_NODES];
__device__ int    d_cur[N_NODES];
__device__ int    d_offs[N_NODES + 1];
__device__ float  d_dinv[N_NODES];
__device__ int    d_bsum[NB];
__device__ int2   d_se[N_EDGES];                     // (src, orig edge id), dst-sorted
__device__ __half2 d_t1h[(size_t)N_NODES * (K1 / 2)];
__device__ __half2 d_t2h[(size_t)N_NODES * (K2 / 2)];
__device__ float  d_h [(size_t)N_NODES * 64];
__device__ __half d_B1h[64 * K1];                    // [n][k] transposed
__device__ __half d_B2h[128 * K2];                   // [n][k] transposed
__device__ float  d_bias2[128];

// ---------------- prep kernels ------------------------------------------------
__global__ void hist_dst(const int* __restrict__ ei) {
    int e = blockIdx.x * blockDim.x + threadIdx.x;
    if (e < N_EDGES) atomicAdd(&d_cnt[ei[N_EDGES + e]], 1);
}

// block sums of counts
__global__ void scan_blk() {
    __shared__ int ws[8];
    int i = blockIdx.x * 256 + threadIdx.x;
    int v = (i < N_NODES) ? d_cnt[i] : 0;
    int lane = threadIdx.x & 31, w = threadIdx.x >> 5;
    int s = v;
    #pragma unroll
    for (int o = 16; o; o >>= 1) s += __shfl_xor_sync(0xffffffffu, s, o);
    if (lane == 0) ws[w] = s;
    __syncthreads();
    if (threadIdx.x == 0) {
        int t = 0;
        #pragma unroll
        for (int j = 0; j < 8; ++j) t += ws[j];
        d_bsum[blockIdx.x] = t;
    }
}

// final scan: each block computes its base from d_bsum then local exclusive scan
__global__ void scan_fin() {
    __shared__ int sh1[8];
    __shared__ int sh2[8];
    __shared__ int bbase;
    int t = threadIdx.x, lane = t & 31, w = t >> 5;

    // block base = sum of d_bsum[0..bid)
    int off = (t < blockIdx.x) ? d_bsum[t] : 0;   // NB=161 <= 256
    #pragma unroll
    for (int o = 16; o; o >>= 1) off += __shfl_xor_sync(0xffffffffu, off, o);
    if (lane == 0) sh1[w] = off;
    __syncthreads();
    if (t == 0) {
        int s = 0;
        #pragma unroll
        for (int j = 0; j < 8; ++j) s += sh1[j];
        bbase = s;
    }
    __syncthreads();

    int i = blockIdx.x * 256 + t;
    int v = (i < N_NODES) ? d_cnt[i] : 0;
    int s = v;
    #pragma unroll
    for (int o = 1; o < 32; o <<= 1) {
        int n = __shfl_up_sync(0xffffffffu, s, o);
        if (lane >= o) s += n;
    }
    if (lane == 31) sh2[w] = s;
    __syncthreads();
    if (w == 0 && lane < 8) {
        int x = sh2[lane];
        #pragma unroll
        for (int o = 1; o < 8; o <<= 1) {
            int n = __shfl_up_sync(0xffu, x, o);
            if (lane >= o) x += n;
        }
        sh2[lane] = x;
    }
    __syncthreads();
    int excl = s - v + (w > 0 ? sh2[w - 1] : 0);
    if (i < N_NODES) {
        d_offs[i] = bbase + excl;
        d_dinv[i] = 1.0f / (float)max(v, 1);
    }
    if (t == 0 && blockIdx.x == 0) d_offs[N_NODES] = N_EDGES;
}

// weave big B matrices (transposed [n][k], half) + bias + zero counters
__global__ void bweave(const float* __restrict__ g1, const float* __restrict__ root1,
                       const float* __restrict__ g2, const float* __restrict__ root2,
                       const float* __restrict__ gs, const float* __restrict__ roots,
                       const float* __restrict__ b2, const float* __restrict__ bs) {
    int idx = blockIdx.x * blockDim.x + threadIdx.x;
    if (idx < N_NODES) { d_cnt[idx] = 0; d_cur[idx] = 0; }
    if (idx < 128) d_bias2[idx] = b2[idx] + bs[idx];
    if (idx < 64 * K1) {
        int n = idx / K1, k = idx % K1;
        float v;
        if (k < 640) v = g1[(k & 63) * 640 + (k >> 6) * 64 + n];
        else         v = root1[(k - 640) * 64 + n];
        d_B1h[idx] = __float2half_rn(v);
    }
    if (idx < 128 * K2) {
        int n = idx / K2, k = idx % K2;
        float v;
        if (k < 640)       v = g2[(k & 63) * 1280 + (k >> 6) * 128 + n];
        else if (k < 704)  v = root2[(k - 640) * 128 + n];
        else if (k < 1344) { int kk = k - 704; v = gs[(kk & 63) * 1280 + (kk >> 6) * 128 + n]; }
        else               v = roots[(k - 1344) * 128 + n];
        d_B2h[idx] = __float2half_rn(v);
    }
}

// dst-sort scatter: (src, edge-id)
__global__ void scatter_idx(const int* __restrict__ ei) {
    int e = blockIdx.x * blockDim.x + threadIdx.x;
    if (e >= N_EDGES) return;
    int src = ei[e];
    int dst = ei[N_EDGES + e];
    int pos = d_offs[dst] + atomicAdd(&d_cur[dst], 1);
    d_se[pos] = make_int2(src, e);
}

// ---------------- t-builds: warp/node, 2-deep gather pipeline -----------------
__global__ __launch_bounds__(256) void tbuild1(
    const float* __restrict__ x, const float* __restrict__ pseudo,
    const float* __restrict__ mu, const float* __restrict__ sg)
{
    int gw = (blockIdx.x * blockDim.x + threadIdx.x) >> 5;
    int lane = threadIdx.x & 31;
    if (gw >= N_NODES) return;

    float m0 = 0.f, m1 = 0.f, i0 = 0.f, i1 = 0.f;
    if (lane < KG) {
        m0 = mu[2 * lane]; m1 = mu[2 * lane + 1];
        float s0 = sg[2 * lane], s1 = sg[2 * lane + 1];
        i0 = -0.5f / (GMM_EPS + s0 * s0);
        i1 = -0.5f / (GMM_EPS + s1 * s1);
    }

    const float2* x2 = (const float2*)x;
    const float2* ps2 = (const float2*)pseudo;
    int beg = d_offs[gw], end = d_offs[gw + 1];
    float dinv = d_dinv[gw];
    float2 a[KG];
    #pragma unroll
    for (int k = 0; k < KG; ++k) a[k] = make_float2(0.f, 0.f);

    if (beg < end) {
        int2 sB = d_se[beg];                               // se for current edge
        int2 sN = (beg + 1 < end) ? d_se[beg + 1] : sB;    // se for next edge
        float2 pC = ps2[sB.y];
        float2 xC = x2[(size_t)sB.x * 32 + lane];
        for (int e = beg; e < end; ++e) {
            float2 pN = pC, xN = xC;
            if (e + 1 < end) {                             // issue next-edge loads now
                pN = ps2[sN.y];
                xN = x2[(size_t)sN.x * 32 + lane];
            }
            int2 sN2 = (e + 2 < end) ? d_se[e + 2] : sN;   // prefetch se two ahead
            float wv = 0.f;
            if (lane < KG) {
                float dx = pC.x - m0, dy = pC.y - m1;
                wv = __expf(dx * dx * i0 + dy * dy * i1);
            }
            #pragma unroll
            for (int k = 0; k < KG; ++k) {
                float w = __shfl_sync(0xffffffffu, wv, k);
                a[k].x = fmaf(w, xC.x, a[k].x);
                a[k].y = fmaf(w, xC.y, a[k].y);
            }
            pC = pN; xC = xN; sN = sN2;
        }
    }
    __half2* tr = d_t1h + (size_t)gw * (K1 / 2);
    #pragma unroll
    for (int k = 0; k < KG; ++k)
        tr[k * 32 + lane] = __floats2half2_rn(a[k].x * dinv, a[k].y * dinv);
    float2 own = x2[(size_t)gw * 32 + lane];
    tr[320 + lane] = __floats2half2_rn(own.x, own.y);
}

__global__ __launch_bounds__(256) void tbuild2(
    const float* __restrict__ x, const float* __restrict__ pseudo,
    const float* __restrict__ mu2, const float* __restrict__ sg2,
    const float* __restrict__ mus, const float* __restrict__ sgs)
{
    int gw = (blockIdx.x * blockDim.x + threadIdx.x) >> 5;
    int lane = threadIdx.x & 31;
    if (gw >= N_NODES) return;

    float m0 = 0.f, m1 = 0.f, i0 = 0.f, i1 = 0.f;
    if (lane < KG) {
        m0 = mu2[2 * lane]; m1 = mu2[2 * lane + 1];
        float s0 = sg2[2 * lane], s1 = sg2[2 * lane + 1];
        i0 = -0.5f / (GMM_EPS + s0 * s0);
        i1 = -0.5f / (GMM_EPS + s1 * s1);
    } else if (lane < 2 * KG) {
        int k = lane - KG;
        m0 = mus[2 * k]; m1 = mus[2 * k + 1];
        float s0 = sgs[2 * k], s1 = sgs[2 * k + 1];
        i0 = -0.5f / (GMM_EPS + s0 * s0);
        i1 = -0.5f / (GMM_EPS + s1 * s1);
    }

    const float2* x2 = (const float2*)x;
    const float2* h2 = (const float2*)d_h;
    const float2* ps2 = (const float2*)pseudo;
    int beg = d_offs[gw], end = d_offs[gw + 1];
    float dinv = d_dinv[gw];
    float2 a2[KG], as_[KG];
    #pragma unroll
    for (int k = 0; k < KG; ++k) { a2[k] = make_float2(0.f, 0.f); as_[k] = make_float2(0.f, 0.f); }

    if (beg < end) {
        int2 sB = d_se[beg];
        int2 sN = (beg + 1 < end) ? d_se[beg + 1] : sB;
        float2 pC = ps2[sB.y];
        float2 hC = h2[(size_t)sB.x * 32 + lane];
        float2 xC = x2[(size_t)sB.x * 32 + lane];
        for (int e = beg; e < end; ++e) {
            float2 pN = pC, hN = hC, xN = xC;
            if (e + 1 < end) {
                pN = ps2[sN.y];
                hN = h2[(size_t)sN.x * 32 + lane];
                xN = x2[(size_t)sN.x * 32 + lane];
            }
            int2 sN2 = (e + 2 < end) ? d_se[e + 2] : sN;
            float wv = 0.f;
            if (lane < 2 * KG) {
                float dx = pC.x - m0, dy = pC.y - m1;
                wv = __expf(dx * dx * i0 + dy * dy * i1);
            }
            #pragma unroll
            for (int k = 0; k < KG; ++k) {
                float w2 = __shfl_sync(0xffffffffu, wv, k);
                float ws = __shfl_sync(0xffffffffu, wv, KG + k);
                a2[k].x  = fmaf(w2, hC.x, a2[k].x);
                a2[k].y  = fmaf(w2, hC.y, a2[k].y);
                as_[k].x = fmaf(ws, xC.x, as_[k].x);
                as_[k].y = fmaf(ws, xC.y, as_[k].y);
            }
            pC = pN; hC = hN; xC = xN; sN = sN2;
        }
    }
    __half2* tr = d_t2h + (size_t)gw * (K2 / 2);
    #pragma unroll
    for (int k = 0; k < KG; ++k) {
        tr[k * 32 + lane]       = __floats2half2_rn(a2[k].x * dinv, a2[k].y * dinv);
        tr[352 + k * 32 + lane] = __floats2half2_rn(as_[k].x * dinv, as_[k].y * dinv);
    }
    float2 hown = h2[(size_t)gw * 32 + lane];
    float2 xown = x2[(size_t)gw * 32 + lane];
    tr[320 + lane] = __floats2half2_rn(hown.x, hown.y);
    tr[672 + lane] = __floats2half2_rn(xown.x, xown.y);
}

// ---------------- fp16 GEMM: BM=BN=64, m16n8k16, cp.async double buffer -------
#define CPA16(dst, src) \
    asm volatile("cp.async.cg.shared.global [%0], [%1], 16;\n" :: "r"(dst), "l"(src))

__global__ __launch_bounds__(256) void gemm_h(
    const __half* __restrict__ A, const __half* __restrict__ Bt,
    float* __restrict__ C, int M, int N, int K, const float* __restrict__ bias)
{
    __shared__ __align__(16) __half As[2][64][72];
    __shared__ __align__(16) __half Bs[2][64][72];
    const int tid = threadIdx.x;
    const int bm = blockIdx.y * 64;
    const int bn = blockIdx.x * 64;
    const int wid = tid >> 5, l = tid & 31;
    const int wr = wid & 3, wc = wid >> 2;     // 4 m-warps x 2 n-warps
    const int tg = l >> 2, ti = l & 3;

    const int row = tid >> 2, q = tid & 3;     // loader: 4 threads/row, 32 B each
    const bool av = (bm + row) < M;
    const __half* apb = A + (size_t)(bm + row) * K + q * 16;
    const __half* bpb = Bt + (size_t)(bn + row) * K + q * 16;
    const unsigned sA0 = (unsigned)__cvta_generic_to_shared(&As[0][row][q * 16]);
    const unsigned sB0 = (unsigned)__cvta_generic_to_shared(&Bs[0][row][q * 16]);
    const unsigned STG = 64 * 72 * 2;          // stage stride in bytes

    auto load_stage = [&](int s, int kt) {
        const __half* a = apb + kt * 64;
        const __half* b = bpb + kt * 64;
        unsigned da = sA0 + s * STG, db = sB0 + s * STG;
        if (av) {
            CPA16(da,      a);
            CPA16(da + 16, a + 8);
        } else {
            *(uint4*)&As[s][row][q * 16]     = make_uint4(0, 0, 0, 0);
            *(uint4*)&As[s][row][q * 16 + 8] = make_uint4(0, 0, 0, 0);
        }
        CPA16(db,      b);
        CPA16(db + 16, b + 8);
        asm volatile("cp.async.commit_group;\n");
    };

    float acc[4][4] = {};
    const int nk = K >> 6;
    load_stage(0, 0);
    for (int kt = 0; kt < nk; ++kt) {
        int cur = kt & 1;
        if (kt + 1 < nk) {
            load_stage(cur ^ 1, kt + 1);
            asm volatile("cp.async.wait_group 1;\n");
        } else {
            asm volatile("cp.async.wait_group 0;\n");
        }
        __syncthreads();
        #pragma unroll
        for (int ks = 0; ks < 4; ++ks) {
            int kb = ks * 16 + 2 * ti;
            unsigned a0 = *(const unsigned*)&As[cur][wr * 16 + tg    ][kb    ];
            unsigned a1 = *(const unsigned*)&As[cur][wr * 16 + tg + 8][kb    ];
            unsigned a2 = *(const unsigned*)&As[cur][wr * 16 + tg    ][kb + 8];
            unsigned a3 = *(const unsigned*)&As[cur][wr * 16 + tg + 8][kb + 8];
            #pragma unroll
            for (int nt = 0; nt < 4; ++nt) {
                int bc = wc * 32 + nt * 8 + tg;
                unsigned b0 = *(const unsigned*)&Bs[cur][bc][kb    ];
                unsigned b1 = *(const unsigned*)&Bs[cur][bc][kb + 8];
                asm volatile(
                    "mma.sync.aligned.m16n8k16.row.col.f32.f16.f16.f32 "
                    "{%0,%1,%2,%3}, {%4,%5,%6,%7}, {%8,%9}, {%0,%1,%2,%3};"
                    : "+f"(acc[nt][0]), "+f"(acc[nt][1]),
                      "+f"(acc[nt][2]), "+f"(acc[nt][3])
                    : "r"(a0), "r"(a1), "r"(a2), "r"(a3), "r"(b0), "r"(b1));
            }
        }
        __syncthreads();
    }
    #pragma unroll
    for (int nt = 0; nt < 4; ++nt) {
        int col = bn + wc * 32 + nt * 8 + 2 * ti;
        float bv0 = bias[col], bv1 = bias[col + 1];
        int r0 = bm + wr * 16 + tg, r1 = r0 + 8;
        if (r0 < M)
            *(float2*)(C + (size_t)r0 * N + col) =
                make_float2(fmaxf(acc[nt][0] + bv0, 0.f), fmaxf(acc[nt][1] + bv1, 0.f));
        if (r1 < M)
            *(float2*)(C + (size_t)r1 * N + col) =
                make_float2(fmaxf(acc[nt][2] + bv0, 0.f), fmaxf(acc[nt][3] + bv1, 0.f));
    }
}

// ---------------- launch ------------------------------------------------------
extern "C" void kernel_launch(void* const* d_in, const int* in_sizes, int n_in,
                              void* d_out, int out_size) {
    const float* x      = (const float*)d_in[0];
    const int*   ei     = (const int*)  d_in[1];
    const float* pseudo = (const float*)d_in[2];
    const float* g1     = (const float*)d_in[3];
    const float* mu1    = (const float*)d_in[4];
    const float* sigma1 = (const float*)d_in[5];
    const float* root1  = (const float*)d_in[6];
    const float* b1     = (const float*)d_in[7];
    const float* g2     = (const float*)d_in[8];
    const float* mu2    = (const float*)d_in[9];
    const float* sigma2 = (const float*)d_in[10];
    const float* root2  = (const float*)d_in[11];
    const float* b2     = (const float*)d_in[12];
    const float* gs     = (const float*)d_in[13];
    const float* mus    = (const float*)d_in[14];
    const float* sigmas = (const float*)d_in[15];
    const float* roots  = (const float*)d_in[16];
    const float* bs     = (const float*)d_in[17];
    float* out = (float*)d_out;

    __half *t1p, *t2p, *B1p, *B2p;
    float *hp, *bias2p;
    cudaGetSymbolAddress((void**)&t1p, d_t1h);
    cudaGetSymbolAddress((void**)&t2p, d_t2h);
    cudaGetSymbolAddress((void**)&hp,  d_h);
    cudaGetSymbolAddress((void**)&B1p, d_B1h);
    cudaGetSymbolAddress((void**)&B2p, d_B2h);
    cudaGetSymbolAddress((void**)&bias2p, d_bias2);

    const int MT = (N_NODES + 63) / 64;
    const int EW = (N_EDGES + 255) / 256;
    const int NW = (N_NODES * 32 + 255) / 256;

    // prep: weave+zero, hist, 2-level scan, scatter
    bweave<<<(128 * K2 + 255) / 256, 256>>>(g1, root1, g2, root2, gs, roots, b2, bs);
    hist_dst<<<EW, 256>>>(ei);
    scan_blk<<<NB, 256>>>();
    scan_fin<<<NB, 256>>>();
    scatter_idx<<<EW, 256>>>(ei);

    // conv1: t1 = [mean-agg(x) | x], h = relu(t1 @ B1 + b1)
    tbuild1<<<NW, 256>>>(x, pseudo, mu1, sigma1);
    gemm_h<<<dim3(1, MT), 256>>>(t1p, B1p, hp, N_NODES, 64, K1, b1);

    // conv2 + shortcut: t2 = [agg(h) | h | agg(x) | x], out = relu(t2 @ B2 + bias)
    tbuild2<<<NW, 256>>>(x, pseudo, mu2, sigma2, mus, sigmas);
    gemm_h<<<dim3(2, MT), 256>>>(t2p, B2p, out, N_NODES, 128, K2, bias2p);
}

// round 9
// speedup vs baseline: 2.8510x; 1.0278x over previous
#include <cuda_runtime.h>
#include <cuda_fp16.h>
#include <math.h>

#define N_NODES 40962
#define N_EDGES 245760
#define KG 10
#define GMM_EPS 1e-15f
#define K1 704      // 640 (agg1) + 64 (x row -> root1)
#define K2 1408     // 640 (agg2) + 64 (h) + 640 (aggs) + 64 (x)
#define NB 161      // scan blocks: ceil(40962/256)

// ---------------- scratch (device globals; no runtime allocation) -------------
__device__ int    d_cnt[N_NODES];
__device__ int    d_cur[N_NODES];
__device__ int    d_offs[N_NODES + 1];
__device__ float  d_dinv[N_NODES];
__device__ int    d_bsum[NB];
__device__ int2   d_se[N_EDGES];                     // (src, orig edge id), dst-sorted
__device__ __half2 d_t1h[(size_t)N_NODES * (K1 / 2)];
__device__ __half2 d_t2h[(size_t)N_NODES * (K2 / 2)];
__device__ float  d_h [(size_t)N_NODES * 64];
__device__ __half d_B1h[64 * K1];                    // [n][k] transposed
__device__ __half d_B2h[128 * K2];                   // [n][k] transposed
__device__ float  d_bias2[128];

// ---------------- prep kernels ------------------------------------------------
__global__ void hist_dst(const int* __restrict__ ei) {
    int e = blockIdx.x * blockDim.x + threadIdx.x;
    if (e < N_EDGES) atomicAdd(&d_cnt[ei[N_EDGES + e]], 1);
}

__global__ void scan_blk() {
    __shared__ int ws[8];
    int i = blockIdx.x * 256 + threadIdx.x;
    int v = (i < N_NODES) ? d_cnt[i] : 0;
    int lane = threadIdx.x & 31, w = threadIdx.x >> 5;
    int s = v;
    #pragma unroll
    for (int o = 16; o; o >>= 1) s += __shfl_xor_sync(0xffffffffu, s, o);
    if (lane == 0) ws[w] = s;
    __syncthreads();
    if (threadIdx.x == 0) {
        int t = 0;
        #pragma unroll
        for (int j = 0; j < 8; ++j) t += ws[j];
        d_bsum[blockIdx.x] = t;
    }
}

__global__ void scan_fin() {
    __shared__ int sh1[8];
    __shared__ int sh2[8];
    __shared__ int bbase;
    int t = threadIdx.x, lane = t & 31, w = t >> 5;

    int off = (t < blockIdx.x) ? d_bsum[t] : 0;   // NB=161 <= 256
    #pragma unroll
    for (int o = 16; o; o >>= 1) off += __shfl_xor_sync(0xffffffffu, off, o);
    if (lane == 0) sh1[w] = off;
    __syncthreads();
    if (t == 0) {
        int s = 0;
        #pragma unroll
        for (int j = 0; j < 8; ++j) s += sh1[j];
        bbase = s;
    }
    __syncthreads();

    int i = blockIdx.x * 256 + t;
    int v = (i < N_NODES) ? d_cnt[i] : 0;
    int s = v;
    #pragma unroll
    for (int o = 1; o < 32; o <<= 1) {
        int n = __shfl_up_sync(0xffffffffu, s, o);
        if (lane >= o) s += n;
    }
    if (lane == 31) sh2[w] = s;
    __syncthreads();
    if (w == 0 && lane < 8) {
        int x = sh2[lane];
        #pragma unroll
        for (int o = 1; o < 8; o <<= 1) {
            int n = __shfl_up_sync(0xffu, x, o);
            if (lane >= o) x += n;
        }
        sh2[lane] = x;
    }
    __syncthreads();
    int excl = s - v + (w > 0 ? sh2[w - 1] : 0);
    if (i < N_NODES) {
        d_offs[i] = bbase + excl;
        d_dinv[i] = 1.0f / (float)max(v, 1);
    }
    if (t == 0 && blockIdx.x == 0) d_offs[N_NODES] = N_EDGES;
}

// weave big B matrices (transposed [n][k], half) + bias + zero counters
__global__ void bweave(const float* __restrict__ g1, const float* __restrict__ root1,
                       const float* __restrict__ g2, const float* __restrict__ root2,
                       const float* __restrict__ gs, const float* __restrict__ roots,
                       const float* __restrict__ b2, const float* __restrict__ bs) {
    int idx = blockIdx.x * blockDim.x + threadIdx.x;
    if (idx < N_NODES) { d_cnt[idx] = 0; d_cur[idx] = 0; }
    if (idx < 128) d_bias2[idx] = b2[idx] + bs[idx];
    if (idx < 64 * K1) {
        int n = idx / K1, k = idx % K1;
        float v;
        if (k < 640) v = g1[(k & 63) * 640 + (k >> 6) * 64 + n];
        else         v = root1[(k - 640) * 64 + n];
        d_B1h[idx] = __float2half_rn(v);
    }
    if (idx < 128 * K2) {
        int n = idx / K2, k = idx % K2;
        float v;
        if (k < 640)       v = g2[(k & 63) * 1280 + (k >> 6) * 128 + n];
        else if (k < 704)  v = root2[(k - 640) * 128 + n];
        else if (k < 1344) { int kk = k - 704; v = gs[(kk & 63) * 1280 + (kk >> 6) * 128 + n]; }
        else               v = roots[(k - 1344) * 128 + n];
        d_B2h[idx] = __float2half_rn(v);
    }
}

// dst-sort scatter: (src, edge-id)
__global__ void scatter_idx(const int* __restrict__ ei) {
    int e = blockIdx.x * blockDim.x + threadIdx.x;
    if (e >= N_EDGES) return;
    int src = ei[e];
    int dst = ei[N_EDGES + e];
    int pos = d_offs[dst] + atomicAdd(&d_cur[dst], 1);
    d_se[pos] = make_int2(src, e);
}

// ---------------- pass X: one x-gather computes agg1 (-> t1) + aggs (-> t2) ---
__global__ __launch_bounds__(256) void tbuildX(
    const float* __restrict__ x, const float* __restrict__ pseudo,
    const float* __restrict__ mu1, const float* __restrict__ sg1,
    const float* __restrict__ mus, const float* __restrict__ sgs)
{
    int gw = (blockIdx.x * blockDim.x + threadIdx.x) >> 5;
    int lane = threadIdx.x & 31;
    if (gw >= N_NODES) return;

    // lanes 0..9: conv1 params; lanes 10..19: shortcut params
    float m0 = 0.f, m1 = 0.f, i0 = 0.f, i1 = 0.f;
    if (lane < KG) {
        m0 = mu1[2 * lane]; m1 = mu1[2 * lane + 1];
        float s0 = sg1[2 * lane], s1 = sg1[2 * lane + 1];
        i0 = -0.5f / (GMM_EPS + s0 * s0);
        i1 = -0.5f / (GMM_EPS + s1 * s1);
    } else if (lane < 2 * KG) {
        int k = lane - KG;
        m0 = mus[2 * k]; m1 = mus[2 * k + 1];
        float s0 = sgs[2 * k], s1 = sgs[2 * k + 1];
        i0 = -0.5f / (GMM_EPS + s0 * s0);
        i1 = -0.5f / (GMM_EPS + s1 * s1);
    }

    const float2* x2 = (const float2*)x;
    const float2* ps2 = (const float2*)pseudo;
    int beg = d_offs[gw], end = d_offs[gw + 1];
    float dinv = d_dinv[gw];
    float2 a1[KG], as_[KG];
    #pragma unroll
    for (int k = 0; k < KG; ++k) { a1[k] = make_float2(0.f, 0.f); as_[k] = make_float2(0.f, 0.f); }

    if (beg < end) {
        int2 sB = d_se[beg];
        int2 sN = (beg + 1 < end) ? d_se[beg + 1] : sB;
        float2 pC = ps2[sB.y];
        float2 xC = x2[(size_t)sB.x * 32 + lane];
        for (int e = beg; e < end; ++e) {
            float2 pN = pC, xN = xC;
            if (e + 1 < end) {
                pN = ps2[sN.y];
                xN = x2[(size_t)sN.x * 32 + lane];
            }
            int2 sN2 = (e + 2 < end) ? d_se[e + 2] : sN;
            float wv = 0.f;
            if (lane < 2 * KG) {
                float dx = pC.x - m0, dy = pC.y - m1;
                wv = __expf(dx * dx * i0 + dy * dy * i1);
            }
            #pragma unroll
            for (int k = 0; k < KG; ++k) {
                float w1 = __shfl_sync(0xffffffffu, wv, k);
                float ws = __shfl_sync(0xffffffffu, wv, KG + k);
                a1[k].x  = fmaf(w1, xC.x, a1[k].x);
                a1[k].y  = fmaf(w1, xC.y, a1[k].y);
                as_[k].x = fmaf(ws, xC.x, as_[k].x);
                as_[k].y = fmaf(ws, xC.y, as_[k].y);
            }
            pC = pN; xC = xN; sN = sN2;
        }
    }
    float2 own = x2[(size_t)gw * 32 + lane];
    __half2* tr1 = d_t1h + (size_t)gw * (K1 / 2);
    #pragma unroll
    for (int k = 0; k < KG; ++k)
        tr1[k * 32 + lane] = __floats2half2_rn(a1[k].x * dinv, a1[k].y * dinv);
    tr1[320 + lane] = __floats2half2_rn(own.x, own.y);

    __half2* tr2 = d_t2h + (size_t)gw * (K2 / 2);
    #pragma unroll
    for (int k = 0; k < KG; ++k)
        tr2[352 + k * 32 + lane] = __floats2half2_rn(as_[k].x * dinv, as_[k].y * dinv);
    tr2[672 + lane] = __floats2half2_rn(own.x, own.y);
}

// ---------------- pass H: h-gather only -> conv2 part of t2 -------------------
__global__ __launch_bounds__(256) void tbuildH(
    const float* __restrict__ pseudo,
    const float* __restrict__ mu2, const float* __restrict__ sg2)
{
    int gw = (blockIdx.x * blockDim.x + threadIdx.x) >> 5;
    int lane = threadIdx.x & 31;
    if (gw >= N_NODES) return;

    float m0 = 0.f, m1 = 0.f, i0 = 0.f, i1 = 0.f;
    if (lane < KG) {
        m0 = mu2[2 * lane]; m1 = mu2[2 * lane + 1];
        float s0 = sg2[2 * lane], s1 = sg2[2 * lane + 1];
        i0 = -0.5f / (GMM_EPS + s0 * s0);
        i1 = -0.5f / (GMM_EPS + s1 * s1);
    }

    const float2* h2 = (const float2*)d_h;
    const float2* ps2 = (const float2*)pseudo;
    int beg = d_offs[gw], end = d_offs[gw + 1];
    float dinv = d_dinv[gw];
    float2 a2[KG];
    #pragma unroll
    for (int k = 0; k < KG; ++k) a2[k] = make_float2(0.f, 0.f);

    if (beg < end) {
        int2 sB = d_se[beg];
        int2 sN = (beg + 1 < end) ? d_se[beg + 1] : sB;
        float2 pC = ps2[sB.y];
        float2 hC = h2[(size_t)sB.x * 32 + lane];
        for (int e = beg; e < end; ++e) {
            float2 pN = pC, hN = hC;
            if (e + 1 < end) {
                pN = ps2[sN.y];
                hN = h2[(size_t)sN.x * 32 + lane];
            }
            int2 sN2 = (e + 2 < end) ? d_se[e + 2] : sN;
            float wv = 0.f;
            if (lane < KG) {
                float dx = pC.x - m0, dy = pC.y - m1;
                wv = __expf(dx * dx * i0 + dy * dy * i1);
            }
            #pragma unroll
            for (int k = 0; k < KG; ++k) {
                float w = __shfl_sync(0xffffffffu, wv, k);
                a2[k].x = fmaf(w, hC.x, a2[k].x);
                a2[k].y = fmaf(w, hC.y, a2[k].y);
            }
            pC = pN; hC = hN; sN = sN2;
        }
    }
    __half2* tr = d_t2h + (size_t)gw * (K2 / 2);
    #pragma unroll
    for (int k = 0; k < KG; ++k)
        tr[k * 32 + lane] = __floats2half2_rn(a2[k].x * dinv, a2[k].y * dinv);
    float2 hown = h2[(size_t)gw * 32 + lane];
    tr[320 + lane] = __floats2half2_rn(hown.x, hown.y);
}

// ---------------- fp16 GEMM: BM=BN=64, m16n8k16, cp.async double buffer -------
#define CPA16(dst, src) \
    asm volatile("cp.async.cg.shared.global [%0], [%1], 16;\n" :: "r"(dst), "l"(src))

__global__ __launch_bounds__(256) void gemm_h(
    const __half* __restrict__ A, const __half* __restrict__ Bt,
    float* __restrict__ C, int M, int N, int K, const float* __restrict__ bias)
{
    __shared__ __align__(16) __half As[2][64][72];
    __shared__ __align__(16) __half Bs[2][64][72];
    const int tid = threadIdx.x;
    const int bm = blockIdx.y * 64;
    const int bn = blockIdx.x * 64;
    const int wid = tid >> 5, l = tid & 31;
    const int wr = wid & 3, wc = wid >> 2;     // 4 m-warps x 2 n-warps
    const int tg = l >> 2, ti = l & 3;

    const int row = tid >> 2, q = tid & 3;
    const bool av = (bm + row) < M;
    const __half* apb = A + (size_t)(bm + row) * K + q * 16;
    const __half* bpb = Bt + (size_t)(bn + row) * K + q * 16;
    const unsigned sA0 = (unsigned)__cvta_generic_to_shared(&As[0][row][q * 16]);
    const unsigned sB0 = (unsigned)__cvta_generic_to_shared(&Bs[0][row][q * 16]);
    const unsigned STG = 64 * 72 * 2;

    auto load_stage = [&](int s, int kt) {
        const __half* a = apb + kt * 64;
        const __half* b = bpb + kt * 64;
        unsigned da = sA0 + s * STG, db = sB0 + s * STG;
        if (av) {
            CPA16(da,      a);
            CPA16(da + 16, a + 8);
        } else {
            *(uint4*)&As[s][row][q * 16]     = make_uint4(0, 0, 0, 0);
            *(uint4*)&As[s][row][q * 16 + 8] = make_uint4(0, 0, 0, 0);
        }
        CPA16(db,      b);
        CPA16(db + 16, b + 8);
        asm volatile("cp.async.commit_group;\n");
    };

    float acc[4][4] = {};
    const int nk = K >> 6;
    load_stage(0, 0);
    for (int kt = 0; kt < nk; ++kt) {
        int cur = kt & 1;
        if (kt + 1 < nk) {
            load_stage(cur ^ 1, kt + 1);
            asm volatile("cp.async.wait_group 1;\n");
        } else {
            asm volatile("cp.async.wait_group 0;\n");
        }
        __syncthreads();
        #pragma unroll
        for (int ks = 0; ks < 4; ++ks) {
            int kb = ks * 16 + 2 * ti;
            unsigned a0 = *(const unsigned*)&As[cur][wr * 16 + tg    ][kb    ];
            unsigned a1 = *(const unsigned*)&As[cur][wr * 16 + tg + 8][kb    ];
            unsigned a2 = *(const unsigned*)&As[cur][wr * 16 + tg    ][kb + 8];
            unsigned a3 = *(const unsigned*)&As[cur][wr * 16 + tg + 8][kb + 8];
            #pragma unroll
            for (int nt = 0; nt < 4; ++nt) {
                int bc = wc * 32 + nt * 8 + tg;
                unsigned b0 = *(const unsigned*)&Bs[cur][bc][kb    ];
                unsigned b1 = *(const unsigned*)&Bs[cur][bc][kb + 8];
                asm volatile(
                    "mma.sync.aligned.m16n8k16.row.col.f32.f16.f16.f32 "
                    "{%0,%1,%2,%3}, {%4,%5,%6,%7}, {%8,%9}, {%0,%1,%2,%3};"
                    : "+f"(acc[nt][0]), "+f"(acc[nt][1]),
                      "+f"(acc[nt][2]), "+f"(acc[nt][3])
                    : "r"(a0), "r"(a1), "r"(a2), "r"(a3), "r"(b0), "r"(b1));
            }
        }
        __syncthreads();
    }
    #pragma unroll
    for (int nt = 0; nt < 4; ++nt) {
        int col = bn + wc * 32 + nt * 8 + 2 * ti;
        float bv0 = bias[col], bv1 = bias[col + 1];
        int r0 = bm + wr * 16 + tg, r1 = r0 + 8;
        if (r0 < M)
            *(float2*)(C + (size_t)r0 * N + col) =
                make_float2(fmaxf(acc[nt][0] + bv0, 0.f), fmaxf(acc[nt][1] + bv1, 0.f));
        if (r1 < M)
            *(float2*)(C + (size_t)r1 * N + col) =
                make_float2(fmaxf(acc[nt][2] + bv0, 0.f), fmaxf(acc[nt][3] + bv1, 0.f));
    }
}

// ---------------- launch ------------------------------------------------------
extern "C" void kernel_launch(void* const* d_in, const int* in_sizes, int n_in,
                              void* d_out, int out_size) {
    const float* x      = (const float*)d_in[0];
    const int*   ei     = (const int*)  d_in[1];
    const float* pseudo = (const float*)d_in[2];
    const float* g1     = (const float*)d_in[3];
    const float* mu1    = (const float*)d_in[4];
    const float* sigma1 = (const float*)d_in[5];
    const float* root1  = (const float*)d_in[6];
    const float* b1     = (const float*)d_in[7];
    const float* g2     = (const float*)d_in[8];
    const float* mu2    = (const float*)d_in[9];
    const float* sigma2 = (const float*)d_in[10];
    const float* root2  = (const float*)d_in[11];
    const float* b2     = (const float*)d_in[12];
    const float* gs     = (const float*)d_in[13];
    const float* mus    = (const float*)d_in[14];
    const float* sigmas = (const float*)d_in[15];
    const float* roots  = (const float*)d_in[16];
    const float* bs     = (const float*)d_in[17];
    float* out = (float*)d_out;

    __half *t1p, *t2p, *B1p, *B2p;
    float *hp, *bias2p;
    cudaGetSymbolAddress((void**)&t1p, d_t1h);
    cudaGetSymbolAddress((void**)&t2p, d_t2h);
    cudaGetSymbolAddress((void**)&hp,  d_h);
    cudaGetSymbolAddress((void**)&B1p, d_B1h);
    cudaGetSymbolAddress((void**)&B2p, d_B2h);
    cudaGetSymbolAddress((void**)&bias2p, d_bias2);

    const int MT = (N_NODES + 63) / 64;
    const int EW = (N_EDGES + 255) / 256;
    const int NW = (N_NODES * 32 + 255) / 256;

    // prep
    bweave<<<(128 * K2 + 255) / 256, 256>>>(g1, root1, g2, root2, gs, roots, b2, bs);
    hist_dst<<<EW, 256>>>(ei);
    scan_blk<<<NB, 256>>>();
    scan_fin<<<NB, 256>>>();
    scatter_idx<<<EW, 256>>>(ei);

    // x-pass: t1 = [agg1(x)|x], t2 back half = [aggs(x)|x]
    tbuildX<<<NW, 256>>>(x, pseudo, mu1, sigma1, mus, sigmas);
    gemm_h<<<dim3(1, MT), 256>>>(t1p, B1p, hp, N_NODES, 64, K1, b1);

    // h-pass: t2 front half = [agg2(h)|h]
    tbuildH<<<NW, 256>>>(pseudo, mu2, sigma2);
    gemm_h<<<dim3(2, MT), 256>>>(t2p, B2p, out, N_NODES, 128, K2, bias2p);
}